// round 4
// baseline (speedup 1.0000x reference)
#include <cuda_runtime.h>

#define N_WIRES 4
#define N_LAYERS 3
#define BATCH 65536
#define BN_EPS 1e-5f
#define PIX_F4 196   // 784 floats = 196 float4 per sample
#define INV196 (1.0f / 196.0f)

// ---- device scratch (no allocations allowed) ----
__device__ float2 g_M[N_LAYERS][N_WIRES][4];   // fused RX@RZ, row-major 2x2
__device__ double g_sum[4];
__device__ double g_sumsq[4];
__device__ float4 g_enc[BATCH];                // per-sample encoding angles

__device__ __forceinline__ float2 cmul(float2 a, float2 b) {
    return make_float2(a.x * b.x - a.y * b.y, a.x * b.y + a.y * b.x);
}
__device__ __forceinline__ float2 cadd(float2 a, float2 b) {
    return make_float2(a.x + b.x, a.y + b.y);
}

template <int D>
__device__ __forceinline__ void apply_gate(float2 s[16], float2 U00, float2 U01,
                                           float2 U10, float2 U11) {
#pragma unroll
    for (int i = 0; i < 16; ++i) {
        if (i & D) continue;
        float2 a = s[i];
        float2 b = s[i | D];
        s[i]     = cadd(cmul(U00, a), cmul(U01, b));
        s[i | D] = cadd(cmul(U10, a), cmul(U11, b));
    }
}

template <int C, int T>
__device__ __forceinline__ void cnot(float2 s[16]) {
#pragma unroll
    for (int i = 0; i < 16; ++i) {
        if (!(i & C) || (i & T)) continue;
        float2 t = s[i];
        s[i] = s[i | T];
        s[i | T] = t;
    }
}

template <int D>
__device__ __forceinline__ void do_wire(float2 st[16], const float2* __restrict__ M,
                                        float c, float s) {
    float2 M0 = M[0], M1 = M[1], M2 = M[2], M3 = M[3];
    float2 U00 = make_float2(M0.x * c + M1.x * s, M0.y * c + M1.y * s);
    float2 U01 = make_float2(M1.x * c - M0.x * s, M1.y * c - M0.y * s);
    float2 U10 = make_float2(M2.x * c + M3.x * s, M2.y * c + M3.y * s);
    float2 U11 = make_float2(M3.x * c - M2.x * s, M3.y * c - M2.y * s);
    apply_gate<D>(st, U00, U01, U10, U11);
}

// ---- kernel 0: zero accumulators + precompute fused gates ----
__global__ void init_kernel(const float* __restrict__ params) {
    int t = threadIdx.x;
    if (t < 4) { g_sum[t] = 0.0; g_sumsq[t] = 0.0; }
    if (t < N_LAYERS * N_WIRES) {
        int l = t / N_WIRES, w = t % N_WIRES;
        float t0 = params[t * 3 + 0];
        float t1 = params[t * 3 + 1];
        float s0, c0, s1, c1;
        sincosf(0.5f * t0, &s0, &c0);
        sincosf(0.5f * t1, &s1, &c1);
        g_M[l][w][0] = make_float2(c1 * c0, -c1 * s0);
        g_M[l][w][1] = make_float2(s1 * s0, -s1 * c0);
        g_M[l][w][2] = make_float2(-s1 * s0, -s1 * c0);
        g_M[l][w][3] = make_float2(c1 * c0, c1 * s0);
    }
}

// ---- kernel 1: encode (pure streaming, float4 loads, warp-per-sample) ----
// grid: 1024 blocks x 256 threads; each warp does 8 consecutive samples.
__global__ __launch_bounds__(256) void encode_kernel(const float4* __restrict__ x4) {
    const int lane = threadIdx.x & 31;
    const int gwarp = (blockIdx.x << 3) + (threadIdx.x >> 5);   // 0..8191

#pragma unroll 2
    for (int it = 0; it < 8; ++it) {
        const int smp = (gwarp << 3) + it;
        const float4* __restrict__ p = x4 + (size_t)smp * PIX_F4;

        float a0 = 0.f, a1 = 0.f, a2 = 0.f, a3 = 0.f;
        float4 f;
        float s;
        // chunk boundaries at float4 indices 49, 98, 147, 196
        f = p[lane];             s = (f.x + f.y) + (f.z + f.w); a0 += s;
        f = p[32 + lane];        s = (f.x + f.y) + (f.z + f.w); if (lane < 17) a0 += s; else a1 += s;
        f = p[64 + lane];        s = (f.x + f.y) + (f.z + f.w); a1 += s;
        f = p[96 + lane];        s = (f.x + f.y) + (f.z + f.w); if (lane < 2)  a1 += s; else a2 += s;
        f = p[128 + lane];       s = (f.x + f.y) + (f.z + f.w); if (lane < 19) a2 += s; else a3 += s;
        f = p[160 + lane];       s = (f.x + f.y) + (f.z + f.w); a3 += s;
        if (lane < 4) {
            f = p[192 + lane];   s = (f.x + f.y) + (f.z + f.w); a3 += s;
        }
#pragma unroll
        for (int o = 16; o; o >>= 1) {
            a0 += __shfl_xor_sync(0xffffffffu, a0, o);
            a1 += __shfl_xor_sync(0xffffffffu, a1, o);
            a2 += __shfl_xor_sync(0xffffffffu, a2, o);
            a3 += __shfl_xor_sync(0xffffffffu, a3, o);
        }
        if (lane == 0)
            g_enc[smp] = make_float4(a0 * INV196, a1 * INV196, a2 * INV196, a3 * INV196);
    }
}

// ---- kernel 2: simulate + linear + partial BN stats (one thread = one sample) ----
__global__ __launch_bounds__(128) void sim_kernel(const float* __restrict__ W,
                                                  const float* __restrict__ b,
                                                  float4* __restrict__ out) {
    __shared__ float s_red[4][8];
    const int tid = threadIdx.x;
    const int wrp = tid >> 5;
    const int lane = tid & 31;
    const int smp = blockIdx.x * 128 + tid;

    float4 e = g_enc[smp];
    float cw[4], sw[4];
    sincosf(0.5f * e.x, &sw[0], &cw[0]);
    sincosf(0.5f * e.y, &sw[1], &cw[1]);
    sincosf(0.5f * e.z, &sw[2], &cw[2]);
    sincosf(0.5f * e.w, &sw[3], &cw[3]);

    float2 st[16];
#pragma unroll
    for (int i = 0; i < 16; ++i) st[i] = make_float2(0.f, 0.f);
    st[0] = make_float2(1.f, 0.f);

#pragma unroll
    for (int l = 0; l < N_LAYERS; ++l) {
        do_wire<1>(st, g_M[l][0], cw[0], sw[0]);
        cnot<1, 2>(st);
        do_wire<2>(st, g_M[l][1], cw[1], sw[1]);
        cnot<2, 4>(st);
        do_wire<4>(st, g_M[l][2], cw[2], sw[2]);
        cnot<4, 8>(st);
        do_wire<8>(st, g_M[l][3], cw[3], sw[3]);
    }

    float z[4] = {0.f, 0.f, 0.f, 0.f};
#pragma unroll
    for (int i = 0; i < 16; ++i) {
        float p = st[i].x * st[i].x + st[i].y * st[i].y;
        z[0] += (i & 1) ? -p : p;
        z[1] += (i & 2) ? -p : p;
        z[2] += (i & 4) ? -p : p;
        z[3] += (i & 8) ? -p : p;
    }

    float o[4];
#pragma unroll
    for (int j = 0; j < 4; ++j) {
        float acc = b[j];
#pragma unroll
        for (int w = 0; w < 4; ++w) acc += z[w] * W[j * 4 + w];
        o[j] = acc;
    }
    out[smp] = make_float4(o[0], o[1], o[2], o[3]);

    // BN partial sums (8 values: sum0..3, sumsq0..3)
    float red[8] = {o[0], o[1], o[2], o[3],
                    o[0] * o[0], o[1] * o[1], o[2] * o[2], o[3] * o[3]};
#pragma unroll
    for (int k = 0; k < 8; ++k) {
        float v = red[k];
#pragma unroll
        for (int off = 16; off; off >>= 1) v += __shfl_xor_sync(0xffffffffu, v, off);
        red[k] = v;
    }
    if (lane == 0) {
#pragma unroll
        for (int k = 0; k < 8; ++k) s_red[wrp][k] = red[k];
    }
    __syncthreads();
    if (tid < 8) {
        float v = s_red[0][tid] + s_red[1][tid] + s_red[2][tid] + s_red[3][tid];
        if (tid < 4) atomicAdd(&g_sum[tid], (double)v);
        else         atomicAdd(&g_sumsq[tid - 4], (double)v);
    }
}

// ---- kernel 3: fold stats + in-place batchnorm (single wave, 2 float4/thread) ----
#define BN_BLOCKS 128
__global__ __launch_bounds__(256) void bn_kernel(float4* __restrict__ out,
                                                 const float* __restrict__ bn_w,
                                                 const float* __restrict__ bn_b) {
    __shared__ float s_scale[4], s_shift[4];
    if (threadIdx.x < 4) {
        int j = threadIdx.x;
        float mu  = (float)(g_sum[j]   * (1.0 / BATCH));
        float ex2 = (float)(g_sumsq[j] * (1.0 / BATCH));
        float var = ex2 - mu * mu;
        float sc = bn_w[j] * rsqrtf(var + BN_EPS);
        s_scale[j] = sc;
        s_shift[j] = bn_b[j] - mu * sc;
    }
    __syncthreads();
    float sc0 = s_scale[0], sc1 = s_scale[1], sc2 = s_scale[2], sc3 = s_scale[3];
    float sh0 = s_shift[0], sh1 = s_shift[1], sh2 = s_shift[2], sh3 = s_shift[3];

    int i = blockIdx.x * 256 + threadIdx.x;
#pragma unroll
    for (int r = 0; r < BATCH / (BN_BLOCKS * 256); ++r) {
        float4 v = out[i];
        v.x = v.x * sc0 + sh0;
        v.y = v.y * sc1 + sh1;
        v.z = v.z * sc2 + sh2;
        v.w = v.w * sc3 + sh3;
        out[i] = v;
        i += BN_BLOCKS * 256;
    }
}

extern "C" void kernel_launch(void* const* d_in, const int* in_sizes, int n_in,
                              void* d_out, int out_size) {
    const float* x      = (const float*)d_in[0];
    const float* params = (const float*)d_in[1];
    const float* W      = (const float*)d_in[2];
    const float* b      = (const float*)d_in[3];
    const float* bn_w   = (const float*)d_in[4];
    const float* bn_b   = (const float*)d_in[5];
    float4* out = (float4*)d_out;

    init_kernel<<<1, 64>>>(params);
    encode_kernel<<<1024, 256>>>((const float4*)x);
    sim_kernel<<<BATCH / 128, 128>>>(W, b, out);
    bn_kernel<<<BN_BLOCKS, 256>>>(out, bn_w, bn_b);
}